// round 11
// baseline (speedup 1.0000x reference)
#include <cuda_runtime.h>

// YOLOv1 loss, fused single pass. R8 structure + 2-pair load batching.
// pred/target: [4096, 7, 7, 90] float32 contiguous. Output: scalar float32.
//
// Grid identical to the proven R8 kernel: 1568 blocks x 4 warps x 16 pairs
// = 100352 pairs = 200704 cells. Only the inner loop changed: each of 8
// iterations loads TWO pairs (12 independent LDG.128 + 4 scalar LDGs,
// batched before any consumption) -> ~12 lines in flight per warp.
// launch_bounds(128,8) gives the 64-reg budget for the wider live set.
//
// Per pair, per lane l:
//   pA/tA = float4 #l               (elements 4l..4l+3, covers 0..127)
//   pB/tB = float4 #(min(l,12)+32)  (elements 128..179; lanes>=13 dummy
//           re-read #44, weighted 0)
//   ct0/ct1 = scalar loads of target elems 4 / 94 (HW broadcast)
// Class + no-obj conf weighted per component via loop-invariant lane masks.
// Box floats (lanes 0-2 -> even slot, lanes 22-24 -> odd slot) staged to
// smem; 32 slots/warp. Phase 2: each lane does box/IoU/select for slot lane.
// Finalize: warp reduce -> block reduce -> atomicAdd (pre-zeroed out).

#define INV_BATCH (1.0f / 4096.0f)
#define WARPS_PER_BLOCK 4
#define NBLOCKS 1568             // 1568*4 = 6272 warps
#define PAIRS_PER_WARP 16        // 6272*16 = 100352 pairs = 200704 cells
#define ITERS 8                  // 2 pairs per iteration

__global__ void yolo_zero_kernel(float* out) {
    if (threadIdx.x == 0) out[0] = 0.0f;
}

__global__ __launch_bounds__(128, 8) void yolo_loss_kernel(
    const float* __restrict__ pred,
    const float* __restrict__ target,
    float* __restrict__ out)
{
    const float inv_s = 1.0f / 7.0f;
    const unsigned FULL = 0xffffffffu;

    const int lane   = threadIdx.x & 31;
    const int wid    = threadIdx.x >> 5;
    const int warp_g = blockIdx.x * WARPS_PER_BLOCK + wid;

    // [warp][cell slot][24 floats]: pred box floats at [0..11], target at
    // [12..23]. Even slots hold elems 0..11, odd slots hold elems 88..99.
    __shared__ float sbuf[WARPS_PER_BLOCK][32][24];

    // Loop-invariant per-lane component metadata for the first float4:
    // element e = 4*lane + j; cell c = (e>=90); m = e - 90*c.
    bool cJ[4], clsJ[4], cnfJ[4];
    #pragma unroll
    for (int j = 0; j < 4; j++) {
        int e = 4 * lane + j;
        int c = (e >= 90) ? 1 : 0;
        int m = e - 90 * c;
        cJ[j]   = (c != 0);
        clsJ[j] = (m >= 10);
        cnfJ[j] = (m == 4) || (m == 9);
    }
    const int  l2     = (lane < 13 ? lane : 12) + 32;  // second float4 index
    const bool b2live = (lane < 13);
    const bool stage0 = (lane <= 2);                    // even-slot box floats
    const bool stage1 = (lane >= 22 && lane <= 24);     // odd-slot box floats
    const int  soff   = stage0 ? 4 * lane : 4 * lane - 88;
    const bool stg    = stage0 | stage1;

    float acc = 0.0f;

    const int pbase = warp_g * PAIRS_PER_WARP;

    // ---------------- Phase 1: 8 iterations x 2 pairs ----------------
    #pragma unroll 1
    for (int it = 0; it < ITERS; it++) {
        const int p0 = pbase + 2 * it;
        const float4* P0 = (const float4*)(pred   + (size_t)p0 * 180);
        const float4* T0 = (const float4*)(target + (size_t)p0 * 180);
        const float4* P1 = (const float4*)(pred   + (size_t)(p0 + 1) * 180);
        const float4* T1 = (const float4*)(target + (size_t)(p0 + 1) * 180);

        // ---- batch ALL loads for both pairs (independent) ----
        float4 pA0 = P0[lane];
        float4 tA0 = T0[lane];
        float4 pB0 = P0[l2];
        float4 tB0 = T0[l2];
        float4 pA1 = P1[lane];
        float4 tA1 = T1[lane];
        float4 pB1 = P1[l2];
        float4 tB1 = T1[l2];
        float ct00 = ((const float*)T0)[4];
        float ct01 = ((const float*)T0)[94];
        float ct10 = ((const float*)T1)[4];
        float ct11 = ((const float*)T1)[94];

        // ---- consume pair 0 ----
        {
            float cm0 = (ct00 > 0.0f)  ? 1.0f : 0.0f;
            float cm1 = (ct01 > 0.0f)  ? 1.0f : 0.0f;
            float nb0 = (ct00 == 0.0f) ? 0.5f : 0.0f;
            float nb1 = (ct01 == 0.0f) ? 0.5f : 0.0f;

            float w0 = clsJ[0] ? (cJ[0] ? cm1 : cm0) : (cnfJ[0] ? (cJ[0] ? nb1 : nb0) : 0.0f);
            float w1 = clsJ[1] ? (cJ[1] ? cm1 : cm0) : (cnfJ[1] ? (cJ[1] ? nb1 : nb0) : 0.0f);
            float w2 = clsJ[2] ? (cJ[2] ? cm1 : cm0) : (cnfJ[2] ? (cJ[2] ? nb1 : nb0) : 0.0f);
            float w3 = clsJ[3] ? (cJ[3] ? cm1 : cm0) : (cnfJ[3] ? (cJ[3] ? nb1 : nb0) : 0.0f);
            float wB = b2live ? cm1 : 0.0f;

            float d0 = pA0.x - tA0.x;
            float d1 = pA0.y - tA0.y;
            float d2 = pA0.z - tA0.z;
            float d3 = pA0.w - tA0.w;
            acc += w0 * d0 * d0 + w1 * d1 * d1 + w2 * d2 * d2 + w3 * d3 * d3;

            float e0 = pB0.x - tB0.x;
            float e1 = pB0.y - tB0.y;
            float e2 = pB0.z - tB0.z;
            float e3 = pB0.w - tB0.w;
            acc += wB * (e0 * e0 + e1 * e1 + e2 * e2 + e3 * e3);

            if (stg) {
                int slot = 4 * it + (stage1 ? 1 : 0);
                *(float4*)&sbuf[wid][slot][soff]      = pA0;
                *(float4*)&sbuf[wid][slot][12 + soff] = tA0;
            }
        }

        // ---- consume pair 1 ----
        {
            float cm0 = (ct10 > 0.0f)  ? 1.0f : 0.0f;
            float cm1 = (ct11 > 0.0f)  ? 1.0f : 0.0f;
            float nb0 = (ct10 == 0.0f) ? 0.5f : 0.0f;
            float nb1 = (ct11 == 0.0f) ? 0.5f : 0.0f;

            float w0 = clsJ[0] ? (cJ[0] ? cm1 : cm0) : (cnfJ[0] ? (cJ[0] ? nb1 : nb0) : 0.0f);
            float w1 = clsJ[1] ? (cJ[1] ? cm1 : cm0) : (cnfJ[1] ? (cJ[1] ? nb1 : nb0) : 0.0f);
            float w2 = clsJ[2] ? (cJ[2] ? cm1 : cm0) : (cnfJ[2] ? (cJ[2] ? nb1 : nb0) : 0.0f);
            float w3 = clsJ[3] ? (cJ[3] ? cm1 : cm0) : (cnfJ[3] ? (cJ[3] ? nb1 : nb0) : 0.0f);
            float wB = b2live ? cm1 : 0.0f;

            float d0 = pA1.x - tA1.x;
            float d1 = pA1.y - tA1.y;
            float d2 = pA1.z - tA1.z;
            float d3 = pA1.w - tA1.w;
            acc += w0 * d0 * d0 + w1 * d1 * d1 + w2 * d2 * d2 + w3 * d3 * d3;

            float e0 = pB1.x - tB1.x;
            float e1 = pB1.y - tB1.y;
            float e2 = pB1.z - tB1.z;
            float e3 = pB1.w - tB1.w;
            acc += wB * (e0 * e0 + e1 * e1 + e2 * e2 + e3 * e3);

            if (stg) {
                int slot = 4 * it + 2 + (stage1 ? 1 : 0);
                *(float4*)&sbuf[wid][slot][soff]      = pA1;
                *(float4*)&sbuf[wid][slot][12 + soff] = tA1;
            }
        }
    }
    __syncwarp();

    // ---------------- Phase 2: box math, one cell per lane ----------------
    {
        const int  sub  = lane & 1;                 // cell within its pair
        const int  boff = sub ? 2 : 0;              // odd slot: elems start at 88
        const float* s = sbuf[wid][lane];

        float pp0 = s[boff + 0],  pp1 = s[boff + 1],  pp2 = s[boff + 2];
        float pp3 = s[boff + 3],  pp4 = s[boff + 4],  pp5 = s[boff + 5];
        float pp6 = s[boff + 6],  pp7 = s[boff + 7],  pp8 = s[boff + 8];
        float pp9 = s[boff + 9];
        float tt0 = s[12 + boff + 0], tt1 = s[12 + boff + 1], tt2 = s[12 + boff + 2];
        float tt3 = s[12 + boff + 3], tt4 = s[12 + boff + 4], tt5 = s[12 + boff + 5];
        float tt6 = s[12 + boff + 6], tt7 = s[12 + boff + 7], tt8 = s[12 + boff + 8];

        float coord_m = (tt4 > 0.0f) ? 1.0f : 0.0f;

        // pred box 0
        float pax0 = pp0 * inv_s - 0.5f * pp2;
        float pay0 = pp1 * inv_s - 0.5f * pp3;
        float pbx0 = pax0 * inv_s + 0.5f * pp2;
        float pby0 = pay0 * inv_s + 0.5f * pp3;
        // pred box 1
        float pax1 = pp5 * inv_s - 0.5f * pp7;
        float pay1 = pp6 * inv_s - 0.5f * pp8;
        float pbx1 = pax1 * inv_s + 0.5f * pp7;
        float pby1 = pay1 * inv_s + 0.5f * pp8;

        // target box 0
        float tax = tt0 * inv_s - 0.5f * tt2;
        float tay = tt1 * inv_s - 0.5f * tt3;
        float tbx = tax * inv_s + 0.5f * tt2;
        float tby = tay * inv_s + 0.5f * tt3;
        float t_area = (tbx - tax) * (tby - tay);

        // IoU box 0
        float w0 = fmaxf(fminf(pbx0, tbx) - fmaxf(pax0, tax), 0.0f);
        float h0 = fmaxf(fminf(pby0, tby) - fmaxf(pay0, tay), 0.0f);
        float inter0 = w0 * h0;
        float parea0 = (pbx0 - pax0) * (pby0 - pay0);
        float iou0 = inter0 / (parea0 + t_area - inter0);
        // IoU box 1
        float w1 = fmaxf(fminf(pbx1, tbx) - fmaxf(pax1, tax), 0.0f);
        float h1 = fmaxf(fminf(pby1, tby) - fmaxf(pay1, tay), 0.0f);
        float inter1 = w1 * h1;
        float parea1 = (pbx1 - pax1) * (pby1 - pay1);
        float iou1 = inter1 / (parea1 + t_area - inter1);

        bool sel1 = (iou1 > iou0);
        float max_iou = sel1 ? iou1 : iou0;

        float psx = sel1 ? pax1 : pax0;
        float psy = sel1 ? pay1 : pay0;
        float psw = sel1 ? pbx1 : pbx0;
        float psh = sel1 ? pby1 : pby0;
        float psc = sel1 ? pp9  : pp4;

        float tsx = sel1 ? tt5 : tax;
        float tsy = sel1 ? tt6 : tay;
        float tsw = sel1 ? tt7 : tbx;
        float tsh = sel1 ? tt8 : tby;

        float ddx = psx - tsx, ddy = psy - tsy;
        float ddw = psw - tsw, ddh = psh - tsh;
        float xy_wh = ddx * ddx + ddy * ddy + ddw * ddw + ddh * ddh;
        float dc = psc - max_iou;

        acc += coord_m * (5.0f * xy_wh + dc * dc);
    }

    // ---------------- final reduction ----------------
    #pragma unroll
    for (int o = 16; o > 0; o >>= 1)
        acc += __shfl_xor_sync(FULL, acc, o);

    __shared__ float wsum[WARPS_PER_BLOCK];
    if (lane == 0) wsum[wid] = acc;
    __syncthreads();
    if (threadIdx.x == 0) {
        float tot = 0.0f;
        #pragma unroll
        for (int i = 0; i < WARPS_PER_BLOCK; i++) tot += wsum[i];
        atomicAdd(out, tot * INV_BATCH);
    }
}

extern "C" void kernel_launch(void* const* d_in, const int* in_sizes, int n_in,
                              void* d_out, int out_size) {
    const float* pred   = (const float*)d_in[0];
    const float* target = (const float*)d_in[1];
    float* out = (float*)d_out;
    (void)in_sizes; (void)n_in; (void)out_size;

    yolo_zero_kernel<<<1, 32>>>(out);
    yolo_loss_kernel<<<NBLOCKS, 128>>>(pred, target, out);
}

// round 12
// speedup vs baseline: 1.1677x; 1.1677x over previous
#include <cuda_runtime.h>

// YOLOv1 loss, fused single pass. R8 inner loop (1 pair/iter, 38 regs),
// re-tiled for higher occupancy.
// pred/target: [4096, 7, 7, 90] float32 contiguous. Output: scalar float32.
//
// 3136 blocks x 4 warps x 8 pairs = 100352 pairs = 200704 cells, exact.
// launch_bounds(128,12): 42-reg budget (R8 needed 38), 12 blocks/SM ->
// 48 warps/SM resident, ~1.6 waves of small blocks (smooth tail).
//
// Per pair, per lane l (all loads unconditional & independent, no shfl):
//   pA/tA = float4 #l               (elements 4l..4l+3, covers 0..127)
//   pB/tB = float4 #(min(l,12)+32)  (elements 128..179; lanes>=13 dummy
//           re-read #44, weighted 0)
//   ct0/ct1 = scalar loads of target elems 4 / 94 (HW broadcast)
// Class + no-obj conf weighted per component via loop-invariant lane masks.
// Box floats (lanes 0-2 -> even slot, lanes 22-24 -> odd slot) staged to
// smem; 16 slots/warp. Phase 2: lanes 0-15 do box/IoU/select math.
// Finalize: warp reduce -> block reduce -> atomicAdd (pre-zeroed out).

#define INV_BATCH (1.0f / 4096.0f)
#define WARPS_PER_BLOCK 4
#define NBLOCKS 3136             // 3136*4 = 12544 warps
#define PAIRS_PER_WARP 8         // 12544*8 = 100352 pairs = 200704 cells

__global__ void yolo_zero_kernel(float* out) {
    if (threadIdx.x == 0) out[0] = 0.0f;
}

__global__ __launch_bounds__(128, 12) void yolo_loss_kernel(
    const float* __restrict__ pred,
    const float* __restrict__ target,
    float* __restrict__ out)
{
    const float inv_s = 1.0f / 7.0f;
    const unsigned FULL = 0xffffffffu;

    const int lane   = threadIdx.x & 31;
    const int wid    = threadIdx.x >> 5;
    const int warp_g = blockIdx.x * WARPS_PER_BLOCK + wid;

    // [warp][cell slot][24 floats]: pred box floats at [0..11], target at
    // [12..23]. Even slots hold elems 0..11, odd slots hold elems 88..99.
    __shared__ float sbuf[WARPS_PER_BLOCK][16][24];

    // Loop-invariant per-lane component metadata for the first float4:
    // element e = 4*lane + j; cell c = (e>=90); m = e - 90*c.
    bool cJ[4], clsJ[4], cnfJ[4];
    #pragma unroll
    for (int j = 0; j < 4; j++) {
        int e = 4 * lane + j;
        int c = (e >= 90) ? 1 : 0;
        int m = e - 90 * c;
        cJ[j]   = (c != 0);
        clsJ[j] = (m >= 10);
        cnfJ[j] = (m == 4) || (m == 9);
    }
    const int  l2     = (lane < 13 ? lane : 12) + 32;  // second float4 index
    const bool b2live = (lane < 13);
    const bool stage0 = (lane <= 2);                    // even-slot box floats
    const bool stage1 = (lane >= 22 && lane <= 24);     // odd-slot box floats
    const int  soff   = stage0 ? 4 * lane : 4 * lane - 88;
    const bool stg    = stage0 | stage1;

    float acc = 0.0f;

    const int pbase = warp_g * PAIRS_PER_WARP;

    // ---------------- Phase 1: stream 8 contiguous pairs ----------------
    #pragma unroll 1
    for (int i = 0; i < PAIRS_PER_WARP; i++) {
        const int p = pbase + i;
        const float4* P = (const float4*)(pred   + (size_t)p * 180);
        const float4* T = (const float4*)(target + (size_t)p * 180);

        // 6 independent loads, no cross-lane deps
        float4 pA = P[lane];
        float4 tA = T[lane];
        float4 pB = P[l2];
        float4 tB = T[l2];
        float  ct0 = ((const float*)T)[4];    // conf_t of cell 2p
        float  ct1 = ((const float*)T)[94];   // conf_t of cell 2p+1

        float cm0 = (ct0 > 0.0f)  ? 1.0f : 0.0f;
        float cm1 = (ct1 > 0.0f)  ? 1.0f : 0.0f;
        float nb0 = (ct0 == 0.0f) ? 0.5f : 0.0f;
        float nb1 = (ct1 == 0.0f) ? 0.5f : 0.0f;

        // per-component weights (loop-invariant masks -> FSELs)
        float w0 = clsJ[0] ? (cJ[0] ? cm1 : cm0) : (cnfJ[0] ? (cJ[0] ? nb1 : nb0) : 0.0f);
        float w1 = clsJ[1] ? (cJ[1] ? cm1 : cm0) : (cnfJ[1] ? (cJ[1] ? nb1 : nb0) : 0.0f);
        float w2 = clsJ[2] ? (cJ[2] ? cm1 : cm0) : (cnfJ[2] ? (cJ[2] ? nb1 : nb0) : 0.0f);
        float w3 = clsJ[3] ? (cJ[3] ? cm1 : cm0) : (cnfJ[3] ? (cJ[3] ? nb1 : nb0) : 0.0f);
        float wB = b2live ? cm1 : 0.0f;       // elems 128..179: all class, cell1

        float d0 = pA.x - tA.x;
        float d1 = pA.y - tA.y;
        float d2 = pA.z - tA.z;
        float d3 = pA.w - tA.w;
        acc += w0 * d0 * d0 + w1 * d1 * d1 + w2 * d2 * d2 + w3 * d3 * d3;

        float e0 = pB.x - tB.x;
        float e1 = pB.y - tB.y;
        float e2 = pB.z - tB.z;
        float e3 = pB.w - tB.w;
        acc += wB * (e0 * e0 + e1 * e1 + e2 * e2 + e3 * e3);

        // stage box floats
        if (stg) {
            int slot = 2 * i + (stage1 ? 1 : 0);
            *(float4*)&sbuf[wid][slot][soff]      = pA;
            *(float4*)&sbuf[wid][slot][12 + soff] = tA;
        }
    }
    __syncwarp();

    // ---------------- Phase 2: box math, one cell per lane (0-15) ----------------
    if (lane < 16) {
        const int  sub  = lane & 1;
        const int  boff = sub ? 2 : 0;              // odd slot: elems start at 88
        const float* s = sbuf[wid][lane];

        float pp0 = s[boff + 0],  pp1 = s[boff + 1],  pp2 = s[boff + 2];
        float pp3 = s[boff + 3],  pp4 = s[boff + 4],  pp5 = s[boff + 5];
        float pp6 = s[boff + 6],  pp7 = s[boff + 7],  pp8 = s[boff + 8];
        float pp9 = s[boff + 9];
        float tt0 = s[12 + boff + 0], tt1 = s[12 + boff + 1], tt2 = s[12 + boff + 2];
        float tt3 = s[12 + boff + 3], tt4 = s[12 + boff + 4], tt5 = s[12 + boff + 5];
        float tt6 = s[12 + boff + 6], tt7 = s[12 + boff + 7], tt8 = s[12 + boff + 8];

        float coord_m = (tt4 > 0.0f) ? 1.0f : 0.0f;

        // pred box 0
        float pax0 = pp0 * inv_s - 0.5f * pp2;
        float pay0 = pp1 * inv_s - 0.5f * pp3;
        float pbx0 = pax0 * inv_s + 0.5f * pp2;
        float pby0 = pay0 * inv_s + 0.5f * pp3;
        // pred box 1
        float pax1 = pp5 * inv_s - 0.5f * pp7;
        float pay1 = pp6 * inv_s - 0.5f * pp8;
        float pbx1 = pax1 * inv_s + 0.5f * pp7;
        float pby1 = pay1 * inv_s + 0.5f * pp8;

        // target box 0
        float tax = tt0 * inv_s - 0.5f * tt2;
        float tay = tt1 * inv_s - 0.5f * tt3;
        float tbx = tax * inv_s + 0.5f * tt2;
        float tby = tay * inv_s + 0.5f * tt3;
        float t_area = (tbx - tax) * (tby - tay);

        // IoU box 0
        float w0 = fmaxf(fminf(pbx0, tbx) - fmaxf(pax0, tax), 0.0f);
        float h0 = fmaxf(fminf(pby0, tby) - fmaxf(pay0, tay), 0.0f);
        float inter0 = w0 * h0;
        float parea0 = (pbx0 - pax0) * (pby0 - pay0);
        float iou0 = inter0 / (parea0 + t_area - inter0);
        // IoU box 1
        float w1 = fmaxf(fminf(pbx1, tbx) - fmaxf(pax1, tax), 0.0f);
        float h1 = fmaxf(fminf(pby1, tby) - fmaxf(pay1, tay), 0.0f);
        float inter1 = w1 * h1;
        float parea1 = (pbx1 - pax1) * (pby1 - pay1);
        float iou1 = inter1 / (parea1 + t_area - inter1);

        bool sel1 = (iou1 > iou0);
        float max_iou = sel1 ? iou1 : iou0;

        float psx = sel1 ? pax1 : pax0;
        float psy = sel1 ? pay1 : pay0;
        float psw = sel1 ? pbx1 : pbx0;
        float psh = sel1 ? pby1 : pby0;
        float psc = sel1 ? pp9  : pp4;

        float tsx = sel1 ? tt5 : tax;
        float tsy = sel1 ? tt6 : tay;
        float tsw = sel1 ? tt7 : tbx;
        float tsh = sel1 ? tt8 : tby;

        float ddx = psx - tsx, ddy = psy - tsy;
        float ddw = psw - tsw, ddh = psh - tsh;
        float xy_wh = ddx * ddx + ddy * ddy + ddw * ddw + ddh * ddh;
        float dc = psc - max_iou;

        acc += coord_m * (5.0f * xy_wh + dc * dc);
    }

    // ---------------- final reduction ----------------
    #pragma unroll
    for (int o = 16; o > 0; o >>= 1)
        acc += __shfl_xor_sync(FULL, acc, o);

    __shared__ float wsum[WARPS_PER_BLOCK];
    if (lane == 0) wsum[wid] = acc;
    __syncthreads();
    if (threadIdx.x == 0) {
        float tot = 0.0f;
        #pragma unroll
        for (int i = 0; i < WARPS_PER_BLOCK; i++) tot += wsum[i];
        atomicAdd(out, tot * INV_BATCH);
    }
}

extern "C" void kernel_launch(void* const* d_in, const int* in_sizes, int n_in,
                              void* d_out, int out_size) {
    const float* pred   = (const float*)d_in[0];
    const float* target = (const float*)d_in[1];
    float* out = (float*)d_out;
    (void)in_sizes; (void)n_in; (void)out_size;

    yolo_zero_kernel<<<1, 32>>>(out);
    yolo_loss_kernel<<<NBLOCKS, 128>>>(pred, target, out);
}